// round 14
// baseline (speedup 1.0000x reference)
#include <cuda_runtime.h>
#include <math.h>

#define D_MODEL 1024
#define D_FF    2816
#define NHEADS  16
#define DK      64
#define BATCH   2
#define SEQ     2048
#define BSROWS  (BATCH*SEQ)   // 4096
#define EPSV    1e-5f

// ---------------- scratch (no cudaMalloc allowed) ----------------
static __device__ float g_h   [(size_t)BSROWS*D_MODEL];
static __device__ float g_q   [(size_t)BSROWS*D_MODEL];
static __device__ float g_k   [(size_t)BSROWS*D_MODEL];
static __device__ float g_v   [(size_t)BSROWS*D_MODEL];
static __device__ float g_attn[(size_t)BSROWS*D_MODEL];
static __device__ float g_y   [(size_t)BSROWS*D_MODEL];
static __device__ float g_u   [(size_t)BSROWS*D_FF];
static __device__ float g_g   [(size_t)BSROWS*D_FF];

// ---------------- common MMA helpers ----------------
__device__ __forceinline__ unsigned f2tf32(float f) {
    unsigned u;
    asm("cvt.rna.tf32.f32 %0, %1;\n" : "=r"(u) : "f"(f));
    return u;
}

__device__ __forceinline__ void mma_tf32(float* d, const unsigned* a, const unsigned* b) {
    asm volatile(
        "mma.sync.aligned.m16n8k8.row.col.f32.tf32.tf32.f32 "
        "{%0,%1,%2,%3}, {%4,%5,%6,%7}, {%8,%9}, {%0,%1,%2,%3};\n"
        : "+f"(d[0]), "+f"(d[1]), "+f"(d[2]), "+f"(d[3])
        : "r"(a[0]), "r"(a[1]), "r"(a[2]), "r"(a[3]), "r"(b[0]), "r"(b[1]));
}

__device__ __forceinline__ void cp_a16(unsigned d, const float* s) {
    asm volatile("cp.async.cg.shared.global [%0], [%1], 16;\n" :: "r"(d), "l"(s));
}

// ---------------- RMSNorm: one block per row ----------------
__global__ void rmsnorm_k(const float* __restrict__ x, const float* __restrict__ gains,
                          float* __restrict__ o) {
    int row = blockIdx.x;
    const float* xr = x + (size_t)row * D_MODEL;
    float*       orow = o + (size_t)row * D_MODEL;
    float s = 0.f;
    for (int i = threadIdx.x; i < D_MODEL; i += 256) { float v = xr[i]; s += v * v; }
    #pragma unroll
    for (int off = 16; off; off >>= 1) s += __shfl_xor_sync(0xffffffffu, s, off);
    __shared__ float ws[8];
    __shared__ float rinv;
    if ((threadIdx.x & 31) == 0) ws[threadIdx.x >> 5] = s;
    __syncthreads();
    if (threadIdx.x == 0) {
        float t = 0.f;
        #pragma unroll
        for (int i = 0; i < 8; i++) t += ws[i];
        rinv = rsqrtf(t / (float)D_MODEL + EPSV);
    }
    __syncthreads();
    float r = rinv;
    for (int i = threadIdx.x; i < D_MODEL; i += 256)
        orow[i] = xr[i] * gains[i] * r;
}

// ---------------- TF32 GEMM core: cp.async 3-stage, K-chunk 32 ----------------
// C[128,128 tile] = A[M,K] * B[N,K]^T (+res / rope). fp32 bits fed directly to
// mma.tf32 (HW RZ truncation). Smem row stride 36 words.
// Fragment k-slots are fed with a per-8-group permutation (slot pair (tig,tig+4)
// <- physical cols (2*tig, 2*tig+1)) applied identically to A and B, which makes
// every fragment load a single LDS.64 of adjacent words. Bit-exact same result.
#define KSTG (128 * 36)                 // words per matrix per stage
#define GEMM_SMEM (3 * 2 * KSTG * 4)    // 110592 bytes

__device__ __forceinline__ void gemm_core(const float* __restrict__ A,
                                          const float* __restrict__ B,
                                          const float* __restrict__ res,
                                          float* __restrict__ C,
                                          int N, int K, int bm, int bn, int rope) {
    extern __shared__ unsigned smg[];
    const int t = threadIdx.x;
    const int warp = t >> 5, lane = t & 31;
    const int gid = lane >> 2, tig = lane & 3;
    const int wm = (warp >> 2) * 64, wn = (warp & 3) * 32;

    const int arow = t >> 3;         // 0..31
    const int ac4  = (t & 7) * 4;    // 0..28
    const float* Ag = A + (size_t)(bm + arow) * K + ac4;
    const float* Bg = B + (size_t)(bn + arow) * K + ac4;
    unsigned sbase = (unsigned)__cvta_generic_to_shared(smg);

    auto issue = [&](int s, int kof) {
        unsigned abase = sbase + (unsigned)(s * 2 * KSTG) * 4u;
        unsigned bbase = abase + (unsigned)KSTG * 4u;
        #pragma unroll
        for (int i = 0; i < 4; i++) {
            unsigned off = (unsigned)((arow + i * 32) * 36 + ac4) * 4u;
            cp_a16(abase + off, Ag + (size_t)(i * 32) * K + kof);
            cp_a16(bbase + off, Bg + (size_t)(i * 32) * K + kof);
        }
        asm volatile("cp.async.commit_group;\n" ::: "memory");
    };

    float acc[4][4][4];
    #pragma unroll
    for (int i = 0; i < 4; i++)
        #pragma unroll
        for (int j = 0; j < 4; j++)
            #pragma unroll
            for (int r = 0; r < 4; r++) acc[i][j][r] = 0.f;

    const int T = K >> 5;
    issue(0, 0);
    if (T > 1) issue(1, 32);

    int st = 0;   // stage index = kt % 3
    for (int kt = 0; kt < T; kt++) {
        if (kt + 1 < T) {
            asm volatile("cp.async.wait_group 1;\n" ::: "memory");
        } else {
            asm volatile("cp.async.wait_group 0;\n" ::: "memory");
        }
        __syncthreads();   // stage kt visible; all warps done with stage kt-1
        if (kt + 2 < T) {
            int s2 = st + 2; if (s2 >= 3) s2 -= 3;
            issue(s2, (kt + 2) * 32);
        }
        const unsigned* As = smg + st * 2 * KSTG;
        const unsigned* Bs = As + KSTG;
        #pragma unroll
        for (int ks = 0; ks < 4; ks++) {
            const int ko = ks * 8 + tig * 2;
            unsigned af[4][4];
            #pragma unroll
            for (int mt = 0; mt < 4; mt++) {
                int r = wm + mt * 16 + gid;
                uint2 lo = *(const uint2*)&As[r * 36 + ko];
                uint2 hi = *(const uint2*)&As[(r + 8) * 36 + ko];
                af[mt][0] = lo.x; af[mt][2] = lo.y;
                af[mt][1] = hi.x; af[mt][3] = hi.y;
            }
            unsigned bf[4][2];
            #pragma unroll
            for (int nt = 0; nt < 4; nt++) {
                int c = wn + nt * 8 + gid;
                uint2 bb = *(const uint2*)&Bs[c * 36 + ko];
                bf[nt][0] = bb.x; bf[nt][1] = bb.y;
            }
            #pragma unroll
            for (int mt = 0; mt < 4; mt++)
                #pragma unroll
                for (int nt = 0; nt < 4; nt++)
                    mma_tf32(acc[mt][nt], af[mt], bf[nt]);
        }
        if (++st >= 3) st = 0;
    }

    // epilogue
    #pragma unroll
    for (int mt = 0; mt < 4; mt++) {
        int r0 = bm + wm + mt * 16 + gid;
        #pragma unroll
        for (int nt = 0; nt < 4; nt++) {
            int c0 = bn + wn + nt * 8 + tig * 2;
            float2 v0 = make_float2(acc[mt][nt][0], acc[mt][nt][1]);
            float2 v1 = make_float2(acc[mt][nt][2], acc[mt][nt][3]);
            if (rope) {
                int d = c0 & 63;   // even; pair (d, d+1), j = d/2
                float inv = expf(-(float)d * (9.210340371976184f / 64.f));
                float sn0, cs0, sn1, cs1;
                sincosf((float)(r0 & (SEQ - 1)) * inv, &sn0, &cs0);
                sincosf((float)((r0 + 8) & (SEQ - 1)) * inv, &sn1, &cs1);
                float t0 = v0.x * cs0 - v0.y * sn0;
                v0.y = v0.y * cs0 + v0.x * sn0; v0.x = t0;
                float t1 = v1.x * cs1 - v1.y * sn1;
                v1.y = v1.y * cs1 + v1.x * sn1; v1.x = t1;
            } else if (res) {
                float2 r0v = *(const float2*)&res[(size_t)r0 * N + c0];
                float2 r1v = *(const float2*)&res[(size_t)(r0 + 8) * N + c0];
                v0.x += r0v.x; v0.y += r0v.y;
                v1.x += r1v.x; v1.y += r1v.y;
            }
            *(float2*)&C[(size_t)r0 * N + c0]       = v0;
            *(float2*)&C[(size_t)(r0 + 8) * N + c0] = v1;
        }
    }
}

__global__ __launch_bounds__(256, 2) void gemm_plain(const float* __restrict__ A,
                                                     const float* __restrict__ B,
                                                     const float* __restrict__ res,
                                                     float* __restrict__ C,
                                                     int N, int K) {
    gemm_core(A, B, res, C, N, K, blockIdx.y * 128, blockIdx.x * 128, 0);
}

// fused QKV: grid.x = 24 (8 per matrix); RoPE fused for Q,K
__global__ __launch_bounds__(256, 2) void gemm_qkv(const float* __restrict__ A,
                                                   const float* __restrict__ WQ,
                                                   const float* __restrict__ WK,
                                                   const float* __restrict__ WV,
                                                   float* __restrict__ q,
                                                   float* __restrict__ k,
                                                   float* __restrict__ v) {
    int sel = blockIdx.x >> 3;
    const float* B = (sel == 0) ? WQ : (sel == 1) ? WK : WV;
    float* C       = (sel == 0) ? q  : (sel == 1) ? k  : v;
    gemm_core(A, B, nullptr, C, D_MODEL, D_MODEL,
              blockIdx.y * 128, (blockIdx.x & 7) * 128, sel < 2);
}

// fused FFN up/gate: grid.x = 44 (22 per matrix)
__global__ __launch_bounds__(256, 2) void gemm_ug(const float* __restrict__ A,
                                                  const float* __restrict__ W1,
                                                  const float* __restrict__ W3,
                                                  float* __restrict__ u,
                                                  float* __restrict__ g) {
    int sel = (blockIdx.x >= 22);
    gemm_core(A, sel ? W3 : W1, nullptr, sel ? g : u, D_FF, D_MODEL,
              blockIdx.y * 128, (blockIdx.x - sel * 22) * 128, 0);
}

// ---------------- Flash attention, TF32 tensor cores (unchanged from R11) ----------------
#define ASTR 68
#define ATTN_SMEM ((128 * ASTR + 2 * 64 * ASTR) * 4)
__global__ __launch_bounds__(256) void attn_mma(const float* __restrict__ q,
                                                const float* __restrict__ k,
                                                const float* __restrict__ v,
                                                float* __restrict__ o) {
    extern __shared__ unsigned sm_u[];
    unsigned* Qs = sm_u;
    unsigned* Ps = sm_u;
    unsigned* Ks = sm_u + 128 * ASTR;
    unsigned* Vs = Ks + 64 * ASTR;

    const int bh = blockIdx.y;
    const int b  = bh / NHEADS, h = bh % NHEADS;
    const int q0 = blockIdx.x * 128;
    const int t  = threadIdx.x;
    const int warp = t >> 5, lane = t & 31;
    const int gid = lane >> 2, tig = lane & 3;
    const int wr  = warp * 16;

    for (int i = t; i < 128 * 16; i += 256) {
        int r = i >> 4, d4 = i & 15;
        float4 qv = *(const float4*)&q[((size_t)(b * SEQ + q0 + r)) * D_MODEL + h * 64 + d4 * 4];
        *(uint4*)&Qs[r * ASTR + d4 * 4] =
            make_uint4(f2tf32(qv.x * 0.125f), f2tf32(qv.y * 0.125f),
                       f2tf32(qv.z * 0.125f), f2tf32(qv.w * 0.125f));
    }
    __syncthreads();

    unsigned qa[8][4];
    #pragma unroll
    for (int ks = 0; ks < 8; ks++) {
        qa[ks][0] = Qs[(wr + gid) * ASTR + ks * 8 + tig];
        qa[ks][1] = Qs[(wr + gid + 8) * ASTR + ks * 8 + tig];
        qa[ks][2] = Qs[(wr + gid) * ASTR + ks * 8 + tig + 4];
        qa[ks][3] = Qs[(wr + gid + 8) * ASTR + ks * 8 + tig + 4];
    }

    float oacc[8][4];
    #pragma unroll
    for (int nt = 0; nt < 8; nt++)
        #pragma unroll
        for (int e = 0; e < 4; e++) oacc[nt][e] = 0.f;
    float m0 = -1e30f, m1 = -1e30f, l0 = 0.f, l1 = 0.f;

    const int r0 = q0 + wr + gid;
    const int r1 = r0 + 8;
    const int ntiles = q0 / 64 + 2;

    for (int kt = 0; kt < ntiles; kt++) {
        const int k0 = kt * 64;
        __syncthreads();
        for (int i = t; i < 64 * 16; i += 256) {
            int r = i >> 4, d4 = i & 15;
            size_t gi = ((size_t)(b * SEQ + k0 + r)) * D_MODEL + h * 64 + d4 * 4;
            float4 kv = *(const float4*)&k[gi];
            *(uint4*)&Ks[r * ASTR + d4 * 4] =
                make_uint4(f2tf32(kv.x), f2tf32(kv.y), f2tf32(kv.z), f2tf32(kv.w));
            float4 vv = *(const float4*)&v[gi];
            Vs[(d4 * 4 + 0) * ASTR + r] = f2tf32(vv.x);
            Vs[(d4 * 4 + 1) * ASTR + r] = f2tf32(vv.y);
            Vs[(d4 * 4 + 2) * ASTR + r] = f2tf32(vv.z);
            Vs[(d4 * 4 + 3) * ASTR + r] = f2tf32(vv.w);
        }
        __syncthreads();

        float sacc[8][4];
        #pragma unroll
        for (int nt = 0; nt < 8; nt++) {
            sacc[nt][0] = sacc[nt][1] = sacc[nt][2] = sacc[nt][3] = 0.f;
            #pragma unroll
            for (int ks = 0; ks < 8; ks++) {
                unsigned kb[2];
                kb[0] = Ks[(nt * 8 + gid) * ASTR + ks * 8 + tig];
                kb[1] = Ks[(nt * 8 + gid) * ASTR + ks * 8 + tig + 4];
                mma_tf32(sacc[nt], qa[ks], kb);
            }
        }

        if (k0 + 63 > q0) {
            #pragma unroll
            for (int nt = 0; nt < 8; nt++) {
                int c0 = k0 + nt * 8 + tig * 2;
                if (c0     > r0) sacc[nt][0] = -1e30f;
                if (c0 + 1 > r0) sacc[nt][1] = -1e30f;
                if (c0     > r1) sacc[nt][2] = -1e30f;
                if (c0 + 1 > r1) sacc[nt][3] = -1e30f;
            }
        }

        float m0loc = -1e30f, m1loc = -1e30f;
        #pragma unroll
        for (int nt = 0; nt < 8; nt++) {
            m0loc = fmaxf(m0loc, fmaxf(sacc[nt][0], sacc[nt][1]));
            m1loc = fmaxf(m1loc, fmaxf(sacc[nt][2], sacc[nt][3]));
        }
        m0loc = fmaxf(m0loc, __shfl_xor_sync(0xffffffffu, m0loc, 1));
        m0loc = fmaxf(m0loc, __shfl_xor_sync(0xffffffffu, m0loc, 2));
        m1loc = fmaxf(m1loc, __shfl_xor_sync(0xffffffffu, m1loc, 1));
        m1loc = fmaxf(m1loc, __shfl_xor_sync(0xffffffffu, m1loc, 2));
        float mn0 = fmaxf(m0, m0loc), mn1 = fmaxf(m1, m1loc);
        float corr0 = __expf(m0 - mn0), corr1 = __expf(m1 - mn1);
        float ps0 = 0.f, ps1 = 0.f;
        #pragma unroll
        for (int nt = 0; nt < 8; nt++) {
            float p0 = __expf(sacc[nt][0] - mn0);
            float p1 = __expf(sacc[nt][1] - mn0);
            float p2 = __expf(sacc[nt][2] - mn1);
            float p3 = __expf(sacc[nt][3] - mn1);
            ps0 += p0 + p1; ps1 += p2 + p3;
            *(uint2*)&Ps[(wr + gid) * ASTR + nt * 8 + tig * 2] =
                make_uint2(f2tf32(p0), f2tf32(p1));
            *(uint2*)&Ps[(wr + gid + 8) * ASTR + nt * 8 + tig * 2] =
                make_uint2(f2tf32(p2), f2tf32(p3));
        }
        ps0 += __shfl_xor_sync(0xffffffffu, ps0, 1);
        ps0 += __shfl_xor_sync(0xffffffffu, ps0, 2);
        ps1 += __shfl_xor_sync(0xffffffffu, ps1, 1);
        ps1 += __shfl_xor_sync(0xffffffffu, ps1, 2);
        l0 = l0 * corr0 + ps0;
        l1 = l1 * corr1 + ps1;
        m0 = mn0; m1 = mn1;
        #pragma unroll
        for (int nt = 0; nt < 8; nt++) {
            oacc[nt][0] *= corr0; oacc[nt][1] *= corr0;
            oacc[nt][2] *= corr1; oacc[nt][3] *= corr1;
        }
        __syncwarp();

        #pragma unroll
        for (int ks = 0; ks < 8; ks++) {
            unsigned pa[4];
            pa[0] = Ps[(wr + gid) * ASTR + ks * 8 + tig];
            pa[1] = Ps[(wr + gid + 8) * ASTR + ks * 8 + tig];
            pa[2] = Ps[(wr + gid) * ASTR + ks * 8 + tig + 4];
            pa[3] = Ps[(wr + gid + 8) * ASTR + ks * 8 + tig + 4];
            #pragma unroll
            for (int nt = 0; nt < 8; nt++) {
                unsigned vb[2];
                vb[0] = Vs[(nt * 8 + gid) * ASTR + ks * 8 + tig];
                vb[1] = Vs[(nt * 8 + gid) * ASTR + ks * 8 + tig + 4];
                mma_tf32(oacc[nt], pa, vb);
            }
        }
    }

    float i0 = 1.f / l0, i1 = 1.f / l1;
    size_t ob0 = ((size_t)(b * SEQ + r0)) * D_MODEL + h * 64;
    size_t ob1 = ((size_t)(b * SEQ + r1)) * D_MODEL + h * 64;
    #pragma unroll
    for (int nt = 0; nt < 8; nt++) {
        int c0 = nt * 8 + tig * 2;
        *(float2*)&o[ob0 + c0] = make_float2(oacc[nt][0] * i0, oacc[nt][1] * i0);
        *(float2*)&o[ob1 + c0] = make_float2(oacc[nt][2] * i1, oacc[nt][3] * i1);
    }
}

// ---------------- SwiGLU elementwise: u <- u*sigmoid(u)*g (float4) ----------------
__global__ void swiglu_k(float4* __restrict__ u, const float4* __restrict__ g) {
    size_t i = (size_t)blockIdx.x * blockDim.x + threadIdx.x;
    if (i < (size_t)BSROWS * D_FF / 4) {
        float4 uv = u[i];
        float4 gv = g[i];
        uv.x = uv.x / (1.f + __expf(-uv.x)) * gv.x;
        uv.y = uv.y / (1.f + __expf(-uv.y)) * gv.y;
        uv.z = uv.z / (1.f + __expf(-uv.z)) * gv.z;
        uv.w = uv.w / (1.f + __expf(-uv.w)) * gv.w;
        u[i] = uv;
    }
}

// ---------------- launch ----------------
extern "C" void kernel_launch(void* const* d_in, const int* in_sizes, int n_in,
                              void* d_out, int out_size) {
    const float* x      = (const float*)d_in[0];
    const float* gains1 = (const float*)d_in[1];
    const float* gains2 = (const float*)d_in[2];
    const float* WQ     = (const float*)d_in[3];
    const float* WK     = (const float*)d_in[4];
    const float* WV     = (const float*)d_in[5];
    const float* WO     = (const float*)d_in[6];
    const float* W1     = (const float*)d_in[7];
    const float* W2     = (const float*)d_in[8];
    const float* W3     = (const float*)d_in[9];
    float* out = (float*)d_out;

    float *h, *q, *k, *v, *attn, *y, *u, *g;
    cudaGetSymbolAddress((void**)&h,    g_h);
    cudaGetSymbolAddress((void**)&q,    g_q);
    cudaGetSymbolAddress((void**)&k,    g_k);
    cudaGetSymbolAddress((void**)&v,    g_v);
    cudaGetSymbolAddress((void**)&attn, g_attn);
    cudaGetSymbolAddress((void**)&y,    g_y);
    cudaGetSymbolAddress((void**)&u,    g_u);
    cudaGetSymbolAddress((void**)&g,    g_g);

    cudaFuncSetAttribute(gemm_plain, cudaFuncAttributeMaxDynamicSharedMemorySize, GEMM_SMEM);
    cudaFuncSetAttribute(gemm_qkv,   cudaFuncAttributeMaxDynamicSharedMemorySize, GEMM_SMEM);
    cudaFuncSetAttribute(gemm_ug,    cudaFuncAttributeMaxDynamicSharedMemorySize, GEMM_SMEM);
    cudaFuncSetAttribute(attn_mma,   cudaFuncAttributeMaxDynamicSharedMemorySize, ATTN_SMEM);

    // 1. pre-attention RMSNorm
    rmsnorm_k<<<BSROWS, 256>>>(x, gains1, h);

    // 2. QKV projections + fused RoPE (one launch)
    gemm_qkv<<<dim3(24, BSROWS / 128), 256, GEMM_SMEM>>>(h, WQ, WK, WV, q, k, v);

    // 3. causal flash attention (TF32 tensor cores)
    attn_mma<<<dim3(SEQ / 128, BATCH * NHEADS), 256, ATTN_SMEM>>>(q, k, v, attn);

    // 4. output projection + residual
    gemm_plain<<<dim3(D_MODEL / 128, BSROWS / 128), 256, GEMM_SMEM>>>(
        attn, WO, x, y, D_MODEL, D_MODEL);

    // 5. pre-FFN RMSNorm
    rmsnorm_k<<<BSROWS, 256>>>(y, gains2, h);

    // 6. FFN up + gate (one launch)
    gemm_ug<<<dim3(44, BSROWS / 128), 256, GEMM_SMEM>>>(h, W1, W3, u, g);

    // 7. SwiGLU
    size_t nsw = (size_t)BSROWS * D_FF / 4;
    swiglu_k<<<(int)((nsw + 255) / 256), 256>>>((float4*)u, (const float4*)g);

    // 8. down projection + residual -> out
    gemm_plain<<<dim3(D_MODEL / 128, BSROWS / 128), 256, GEMM_SMEM>>>(
        u, W2, y, out, D_MODEL, D_FF);
}

// round 15
// speedup vs baseline: 1.1065x; 1.1065x over previous
#include <cuda_runtime.h>
#include <math.h>

#define D_MODEL 1024
#define D_FF    2816
#define NHEADS  16
#define DK      64
#define BATCH   2
#define SEQ     2048
#define BSROWS  (BATCH*SEQ)   // 4096
#define EPSV    1e-5f

// ---------------- scratch (no cudaMalloc allowed) ----------------
static __device__ float g_h   [(size_t)BSROWS*D_MODEL];
static __device__ float g_q   [(size_t)BSROWS*D_MODEL];
static __device__ float g_k   [(size_t)BSROWS*D_MODEL];
static __device__ float g_v   [(size_t)BSROWS*D_MODEL];
static __device__ float g_attn[(size_t)BSROWS*D_MODEL];
static __device__ float g_y   [(size_t)BSROWS*D_MODEL];
static __device__ float g_u   [(size_t)BSROWS*D_FF];
static __device__ float g_g   [(size_t)BSROWS*D_FF];

// ---------------- common MMA helpers ----------------
__device__ __forceinline__ unsigned f2tf32(float f) {
    unsigned u;
    asm("cvt.rna.tf32.f32 %0, %1;\n" : "=r"(u) : "f"(f));
    return u;
}

__device__ __forceinline__ void mma_tf32(float* d, const unsigned* a, const unsigned* b) {
    asm volatile(
        "mma.sync.aligned.m16n8k8.row.col.f32.tf32.tf32.f32 "
        "{%0,%1,%2,%3}, {%4,%5,%6,%7}, {%8,%9}, {%0,%1,%2,%3};\n"
        : "+f"(d[0]), "+f"(d[1]), "+f"(d[2]), "+f"(d[3])
        : "r"(a[0]), "r"(a[1]), "r"(a[2]), "r"(a[3]), "r"(b[0]), "r"(b[1]));
}

__device__ __forceinline__ void cp_a16(unsigned d, const float* s) {
    asm volatile("cp.async.cg.shared.global [%0], [%1], 16;\n" :: "r"(d), "l"(s));
}

// ---------------- RMSNorm: one block per row ----------------
__global__ void rmsnorm_k(const float* __restrict__ x, const float* __restrict__ gains,
                          float* __restrict__ o) {
    int row = blockIdx.x;
    const float* xr = x + (size_t)row * D_MODEL;
    float*       orow = o + (size_t)row * D_MODEL;
    float s = 0.f;
    for (int i = threadIdx.x; i < D_MODEL; i += 256) { float v = xr[i]; s += v * v; }
    #pragma unroll
    for (int off = 16; off; off >>= 1) s += __shfl_xor_sync(0xffffffffu, s, off);
    __shared__ float ws[8];
    __shared__ float rinv;
    if ((threadIdx.x & 31) == 0) ws[threadIdx.x >> 5] = s;
    __syncthreads();
    if (threadIdx.x == 0) {
        float t = 0.f;
        #pragma unroll
        for (int i = 0; i < 8; i++) t += ws[i];
        rinv = rsqrtf(t / (float)D_MODEL + EPSV);
    }
    __syncthreads();
    float r = rinv;
    for (int i = threadIdx.x; i < D_MODEL; i += 256)
        orow[i] = xr[i] * gains[i] * r;
}

// ---------------- TF32 GEMM core: cp.async 3-stage, K-chunk 32 ----------------
// C[128,128 tile] = A[M,K] * B[N,K]^T (+res / rope). fp32 bits fed directly to
// mma.tf32 (HW RZ truncation). Smem row stride 36 words; scalar fragment LDS
// (gid*36 + tig pattern -> all banks distinct, conflict-free; the LDS.64
// permuted variant bank-conflicts and regressed in R14).
#define KSTG (128 * 36)                 // words per matrix per stage
#define GEMM_SMEM (3 * 2 * KSTG * 4)    // 110592 bytes

__device__ __forceinline__ void gemm_core(const float* __restrict__ A,
                                          const float* __restrict__ B,
                                          const float* __restrict__ res,
                                          float* __restrict__ C,
                                          int N, int K, int bm, int bn, int rope) {
    extern __shared__ unsigned smg[];
    const int t = threadIdx.x;
    const int warp = t >> 5, lane = t & 31;
    const int gid = lane >> 2, tig = lane & 3;
    const int wm = (warp >> 2) * 64, wn = (warp & 3) * 32;

    const int arow = t >> 3;         // 0..31
    const int ac4  = (t & 7) * 4;    // 0..28
    const float* Ag = A + (size_t)(bm + arow) * K + ac4;
    const float* Bg = B + (size_t)(bn + arow) * K + ac4;
    unsigned sbase = (unsigned)__cvta_generic_to_shared(smg);

    auto issue = [&](int s, int kof) {
        unsigned abase = sbase + (unsigned)(s * 2 * KSTG) * 4u;
        unsigned bbase = abase + (unsigned)KSTG * 4u;
        #pragma unroll
        for (int i = 0; i < 4; i++) {
            unsigned off = (unsigned)((arow + i * 32) * 36 + ac4) * 4u;
            cp_a16(abase + off, Ag + (size_t)(i * 32) * K + kof);
            cp_a16(bbase + off, Bg + (size_t)(i * 32) * K + kof);
        }
        asm volatile("cp.async.commit_group;\n" ::: "memory");
    };

    float acc[4][4][4];
    #pragma unroll
    for (int i = 0; i < 4; i++)
        #pragma unroll
        for (int j = 0; j < 4; j++)
            #pragma unroll
            for (int r = 0; r < 4; r++) acc[i][j][r] = 0.f;

    const int T = K >> 5;
    issue(0, 0);
    if (T > 1) issue(1, 32);

    int st = 0;   // stage index = kt % 3
    for (int kt = 0; kt < T; kt++) {
        if (kt + 1 < T) {
            asm volatile("cp.async.wait_group 1;\n" ::: "memory");
        } else {
            asm volatile("cp.async.wait_group 0;\n" ::: "memory");
        }
        __syncthreads();   // stage kt visible; all warps done with stage kt's prior use
        if (kt + 2 < T) {
            int s2 = st + 2; if (s2 >= 3) s2 -= 3;
            issue(s2, (kt + 2) * 32);
        }
        const unsigned* As = smg + st * 2 * KSTG;
        const unsigned* Bs = As + KSTG;
        #pragma unroll
        for (int ks = 0; ks < 4; ks++) {
            const int ko = ks * 8;
            unsigned af[4][4];
            #pragma unroll
            for (int mt = 0; mt < 4; mt++) {
                int r = wm + mt * 16 + gid;
                af[mt][0] = As[r * 36 + ko + tig];
                af[mt][1] = As[(r + 8) * 36 + ko + tig];
                af[mt][2] = As[r * 36 + ko + tig + 4];
                af[mt][3] = As[(r + 8) * 36 + ko + tig + 4];
            }
            unsigned bf[4][2];
            #pragma unroll
            for (int nt = 0; nt < 4; nt++) {
                int c = wn + nt * 8 + gid;
                bf[nt][0] = Bs[c * 36 + ko + tig];
                bf[nt][1] = Bs[c * 36 + ko + tig + 4];
            }
            #pragma unroll
            for (int mt = 0; mt < 4; mt++)
                #pragma unroll
                for (int nt = 0; nt < 4; nt++)
                    mma_tf32(acc[mt][nt], af[mt], bf[nt]);
        }
        if (++st >= 3) st = 0;
    }

    // epilogue
    #pragma unroll
    for (int mt = 0; mt < 4; mt++) {
        int r0 = bm + wm + mt * 16 + gid;
        #pragma unroll
        for (int nt = 0; nt < 4; nt++) {
            int c0 = bn + wn + nt * 8 + tig * 2;
            float2 v0 = make_float2(acc[mt][nt][0], acc[mt][nt][1]);
            float2 v1 = make_float2(acc[mt][nt][2], acc[mt][nt][3]);
            if (rope) {
                int d = c0 & 63;   // even; pair (d, d+1), j = d/2
                float inv = expf(-(float)d * (9.210340371976184f / 64.f));
                float sn0, cs0, sn1, cs1;
                sincosf((float)(r0 & (SEQ - 1)) * inv, &sn0, &cs0);
                sincosf((float)((r0 + 8) & (SEQ - 1)) * inv, &sn1, &cs1);
                float t0 = v0.x * cs0 - v0.y * sn0;
                v0.y = v0.y * cs0 + v0.x * sn0; v0.x = t0;
                float t1 = v1.x * cs1 - v1.y * sn1;
                v1.y = v1.y * cs1 + v1.x * sn1; v1.x = t1;
            } else if (res) {
                float2 r0v = *(const float2*)&res[(size_t)r0 * N + c0];
                float2 r1v = *(const float2*)&res[(size_t)(r0 + 8) * N + c0];
                v0.x += r0v.x; v0.y += r0v.y;
                v1.x += r1v.x; v1.y += r1v.y;
            }
            *(float2*)&C[(size_t)r0 * N + c0]       = v0;
            *(float2*)&C[(size_t)(r0 + 8) * N + c0] = v1;
        }
    }
}

__global__ __launch_bounds__(256, 2) void gemm_plain(const float* __restrict__ A,
                                                     const float* __restrict__ B,
                                                     const float* __restrict__ res,
                                                     float* __restrict__ C,
                                                     int N, int K) {
    gemm_core(A, B, res, C, N, K, blockIdx.y * 128, blockIdx.x * 128, 0);
}

// fused QKV: grid.x = 24 (8 per matrix); RoPE fused for Q,K
__global__ __launch_bounds__(256, 2) void gemm_qkv(const float* __restrict__ A,
                                                   const float* __restrict__ WQ,
                                                   const float* __restrict__ WK,
                                                   const float* __restrict__ WV,
                                                   float* __restrict__ q,
                                                   float* __restrict__ k,
                                                   float* __restrict__ v) {
    int sel = blockIdx.x >> 3;
    const float* B = (sel == 0) ? WQ : (sel == 1) ? WK : WV;
    float* C       = (sel == 0) ? q  : (sel == 1) ? k  : v;
    gemm_core(A, B, nullptr, C, D_MODEL, D_MODEL,
              blockIdx.y * 128, (blockIdx.x & 7) * 128, sel < 2);
}

// fused FFN up/gate: grid.x = 44 (22 per matrix)
__global__ __launch_bounds__(256, 2) void gemm_ug(const float* __restrict__ A,
                                                  const float* __restrict__ W1,
                                                  const float* __restrict__ W3,
                                                  float* __restrict__ u,
                                                  float* __restrict__ g) {
    int sel = (blockIdx.x >= 22);
    gemm_core(A, sel ? W3 : W1, nullptr, sel ? g : u, D_FF, D_MODEL,
              blockIdx.y * 128, (blockIdx.x - sel * 22) * 128, 0);
}

// ---------------- Flash attention, TF32 tensor cores (unchanged from R11) ----------------
#define ASTR 68
#define ATTN_SMEM ((128 * ASTR + 2 * 64 * ASTR) * 4)
__global__ __launch_bounds__(256) void attn_mma(const float* __restrict__ q,
                                                const float* __restrict__ k,
                                                const float* __restrict__ v,
                                                float* __restrict__ o) {
    extern __shared__ unsigned sm_u[];
    unsigned* Qs = sm_u;
    unsigned* Ps = sm_u;
    unsigned* Ks = sm_u + 128 * ASTR;
    unsigned* Vs = Ks + 64 * ASTR;

    const int bh = blockIdx.y;
    const int b  = bh / NHEADS, h = bh % NHEADS;
    const int q0 = blockIdx.x * 128;
    const int t  = threadIdx.x;
    const int warp = t >> 5, lane = t & 31;
    const int gid = lane >> 2, tig = lane & 3;
    const int wr  = warp * 16;

    for (int i = t; i < 128 * 16; i += 256) {
        int r = i >> 4, d4 = i & 15;
        float4 qv = *(const float4*)&q[((size_t)(b * SEQ + q0 + r)) * D_MODEL + h * 64 + d4 * 4];
        *(uint4*)&Qs[r * ASTR + d4 * 4] =
            make_uint4(f2tf32(qv.x * 0.125f), f2tf32(qv.y * 0.125f),
                       f2tf32(qv.z * 0.125f), f2tf32(qv.w * 0.125f));
    }
    __syncthreads();

    unsigned qa[8][4];
    #pragma unroll
    for (int ks = 0; ks < 8; ks++) {
        qa[ks][0] = Qs[(wr + gid) * ASTR + ks * 8 + tig];
        qa[ks][1] = Qs[(wr + gid + 8) * ASTR + ks * 8 + tig];
        qa[ks][2] = Qs[(wr + gid) * ASTR + ks * 8 + tig + 4];
        qa[ks][3] = Qs[(wr + gid + 8) * ASTR + ks * 8 + tig + 4];
    }

    float oacc[8][4];
    #pragma unroll
    for (int nt = 0; nt < 8; nt++)
        #pragma unroll
        for (int e = 0; e < 4; e++) oacc[nt][e] = 0.f;
    float m0 = -1e30f, m1 = -1e30f, l0 = 0.f, l1 = 0.f;

    const int r0 = q0 + wr + gid;
    const int r1 = r0 + 8;
    const int ntiles = q0 / 64 + 2;

    for (int kt = 0; kt < ntiles; kt++) {
        const int k0 = kt * 64;
        __syncthreads();
        for (int i = t; i < 64 * 16; i += 256) {
            int r = i >> 4, d4 = i & 15;
            size_t gi = ((size_t)(b * SEQ + k0 + r)) * D_MODEL + h * 64 + d4 * 4;
            float4 kv = *(const float4*)&k[gi];
            *(uint4*)&Ks[r * ASTR + d4 * 4] =
                make_uint4(f2tf32(kv.x), f2tf32(kv.y), f2tf32(kv.z), f2tf32(kv.w));
            float4 vv = *(const float4*)&v[gi];
            Vs[(d4 * 4 + 0) * ASTR + r] = f2tf32(vv.x);
            Vs[(d4 * 4 + 1) * ASTR + r] = f2tf32(vv.y);
            Vs[(d4 * 4 + 2) * ASTR + r] = f2tf32(vv.z);
            Vs[(d4 * 4 + 3) * ASTR + r] = f2tf32(vv.w);
        }
        __syncthreads();

        float sacc[8][4];
        #pragma unroll
        for (int nt = 0; nt < 8; nt++) {
            sacc[nt][0] = sacc[nt][1] = sacc[nt][2] = sacc[nt][3] = 0.f;
            #pragma unroll
            for (int ks = 0; ks < 8; ks++) {
                unsigned kb[2];
                kb[0] = Ks[(nt * 8 + gid) * ASTR + ks * 8 + tig];
                kb[1] = Ks[(nt * 8 + gid) * ASTR + ks * 8 + tig + 4];
                mma_tf32(sacc[nt], qa[ks], kb);
            }
        }

        if (k0 + 63 > q0) {
            #pragma unroll
            for (int nt = 0; nt < 8; nt++) {
                int c0 = k0 + nt * 8 + tig * 2;
                if (c0     > r0) sacc[nt][0] = -1e30f;
                if (c0 + 1 > r0) sacc[nt][1] = -1e30f;
                if (c0     > r1) sacc[nt][2] = -1e30f;
                if (c0 + 1 > r1) sacc[nt][3] = -1e30f;
            }
        }

        float m0loc = -1e30f, m1loc = -1e30f;
        #pragma unroll
        for (int nt = 0; nt < 8; nt++) {
            m0loc = fmaxf(m0loc, fmaxf(sacc[nt][0], sacc[nt][1]));
            m1loc = fmaxf(m1loc, fmaxf(sacc[nt][2], sacc[nt][3]));
        }
        m0loc = fmaxf(m0loc, __shfl_xor_sync(0xffffffffu, m0loc, 1));
        m0loc = fmaxf(m0loc, __shfl_xor_sync(0xffffffffu, m0loc, 2));
        m1loc = fmaxf(m1loc, __shfl_xor_sync(0xffffffffu, m1loc, 1));
        m1loc = fmaxf(m1loc, __shfl_xor_sync(0xffffffffu, m1loc, 2));
        float mn0 = fmaxf(m0, m0loc), mn1 = fmaxf(m1, m1loc);
        float corr0 = __expf(m0 - mn0), corr1 = __expf(m1 - mn1);
        float ps0 = 0.f, ps1 = 0.f;
        #pragma unroll
        for (int nt = 0; nt < 8; nt++) {
            float p0 = __expf(sacc[nt][0] - mn0);
            float p1 = __expf(sacc[nt][1] - mn0);
            float p2 = __expf(sacc[nt][2] - mn1);
            float p3 = __expf(sacc[nt][3] - mn1);
            ps0 += p0 + p1; ps1 += p2 + p3;
            *(uint2*)&Ps[(wr + gid) * ASTR + nt * 8 + tig * 2] =
                make_uint2(f2tf32(p0), f2tf32(p1));
            *(uint2*)&Ps[(wr + gid + 8) * ASTR + nt * 8 + tig * 2] =
                make_uint2(f2tf32(p2), f2tf32(p3));
        }
        ps0 += __shfl_xor_sync(0xffffffffu, ps0, 1);
        ps0 += __shfl_xor_sync(0xffffffffu, ps0, 2);
        ps1 += __shfl_xor_sync(0xffffffffu, ps1, 1);
        ps1 += __shfl_xor_sync(0xffffffffu, ps1, 2);
        l0 = l0 * corr0 + ps0;
        l1 = l1 * corr1 + ps1;
        m0 = mn0; m1 = mn1;
        #pragma unroll
        for (int nt = 0; nt < 8; nt++) {
            oacc[nt][0] *= corr0; oacc[nt][1] *= corr0;
            oacc[nt][2] *= corr1; oacc[nt][3] *= corr1;
        }
        __syncwarp();

        #pragma unroll
        for (int ks = 0; ks < 8; ks++) {
            unsigned pa[4];
            pa[0] = Ps[(wr + gid) * ASTR + ks * 8 + tig];
            pa[1] = Ps[(wr + gid + 8) * ASTR + ks * 8 + tig];
            pa[2] = Ps[(wr + gid) * ASTR + ks * 8 + tig + 4];
            pa[3] = Ps[(wr + gid + 8) * ASTR + ks * 8 + tig + 4];
            #pragma unroll
            for (int nt = 0; nt < 8; nt++) {
                unsigned vb[2];
                vb[0] = Vs[(nt * 8 + gid) * ASTR + ks * 8 + tig];
                vb[1] = Vs[(nt * 8 + gid) * ASTR + ks * 8 + tig + 4];
                mma_tf32(oacc[nt], pa, vb);
            }
        }
    }

    float i0 = 1.f / l0, i1 = 1.f / l1;
    size_t ob0 = ((size_t)(b * SEQ + r0)) * D_MODEL + h * 64;
    size_t ob1 = ((size_t)(b * SEQ + r1)) * D_MODEL + h * 64;
    #pragma unroll
    for (int nt = 0; nt < 8; nt++) {
        int c0 = nt * 8 + tig * 2;
        *(float2*)&o[ob0 + c0] = make_float2(oacc[nt][0] * i0, oacc[nt][1] * i0);
        *(float2*)&o[ob1 + c0] = make_float2(oacc[nt][2] * i1, oacc[nt][3] * i1);
    }
}

// ---------------- SwiGLU elementwise: u <- u*sigmoid(u)*g (float4) ----------------
__global__ void swiglu_k(float4* __restrict__ u, const float4* __restrict__ g) {
    size_t i = (size_t)blockIdx.x * blockDim.x + threadIdx.x;
    if (i < (size_t)BSROWS * D_FF / 4) {
        float4 uv = u[i];
        float4 gv = g[i];
        uv.x = uv.x / (1.f + __expf(-uv.x)) * gv.x;
        uv.y = uv.y / (1.f + __expf(-uv.y)) * gv.y;
        uv.z = uv.z / (1.f + __expf(-uv.z)) * gv.z;
        uv.w = uv.w / (1.f + __expf(-uv.w)) * gv.w;
        u[i] = uv;
    }
}

// ---------------- launch ----------------
extern "C" void kernel_launch(void* const* d_in, const int* in_sizes, int n_in,
                              void* d_out, int out_size) {
    const float* x      = (const float*)d_in[0];
    const float* gains1 = (const float*)d_in[1];
    const float* gains2 = (const float*)d_in[2];
    const float* WQ     = (const float*)d_in[3];
    const float* WK     = (const float*)d_in[4];
    const float* WV     = (const float*)d_in[5];
    const float* WO     = (const float*)d_in[6];
    const float* W1     = (const float*)d_in[7];
    const float* W2     = (const float*)d_in[8];
    const float* W3     = (const float*)d_in[9];
    float* out = (float*)d_out;

    float *h, *q, *k, *v, *attn, *y, *u, *g;
    cudaGetSymbolAddress((void**)&h,    g_h);
    cudaGetSymbolAddress((void**)&q,    g_q);
    cudaGetSymbolAddress((void**)&k,    g_k);
    cudaGetSymbolAddress((void**)&v,    g_v);
    cudaGetSymbolAddress((void**)&attn, g_attn);
    cudaGetSymbolAddress((void**)&y,    g_y);
    cudaGetSymbolAddress((void**)&u,    g_u);
    cudaGetSymbolAddress((void**)&g,    g_g);

    cudaFuncSetAttribute(gemm_plain, cudaFuncAttributeMaxDynamicSharedMemorySize, GEMM_SMEM);
    cudaFuncSetAttribute(gemm_qkv,   cudaFuncAttributeMaxDynamicSharedMemorySize, GEMM_SMEM);
    cudaFuncSetAttribute(gemm_ug,    cudaFuncAttributeMaxDynamicSharedMemorySize, GEMM_SMEM);
    cudaFuncSetAttribute(attn_mma,   cudaFuncAttributeMaxDynamicSharedMemorySize, ATTN_SMEM);

    // 1. pre-attention RMSNorm
    rmsnorm_k<<<BSROWS, 256>>>(x, gains1, h);

    // 2. QKV projections + fused RoPE (one launch)
    gemm_qkv<<<dim3(24, BSROWS / 128), 256, GEMM_SMEM>>>(h, WQ, WK, WV, q, k, v);

    // 3. causal flash attention (TF32 tensor cores)
    attn_mma<<<dim3(SEQ / 128, BATCH * NHEADS), 256, ATTN_SMEM>>>(q, k, v, attn);

    // 4. output projection + residual
    gemm_plain<<<dim3(D_MODEL / 128, BSROWS / 128), 256, GEMM_SMEM>>>(
        attn, WO, x, y, D_MODEL, D_MODEL);

    // 5. pre-FFN RMSNorm
    rmsnorm_k<<<BSROWS, 256>>>(y, gains2, h);

    // 6. FFN up + gate (one launch)
    gemm_ug<<<dim3(44, BSROWS / 128), 256, GEMM_SMEM>>>(h, W1, W3, u, g);

    // 7. SwiGLU
    size_t nsw = (size_t)BSROWS * D_FF / 4;
    swiglu_k<<<(int)((nsw + 255) / 256), 256>>>((float4*)u, (const float4*)g);

    // 8. down projection + residual -> out
    gemm_plain<<<dim3(D_MODEL / 128, BSROWS / 128), 256, GEMM_SMEM>>>(
        u, W2, y, out, D_MODEL, D_FF);
}

// round 16
// speedup vs baseline: 1.1940x; 1.0790x over previous
#include <cuda_runtime.h>
#include <math.h>

#define D_MODEL 1024
#define D_FF    2816
#define NHEADS  16
#define DK      64
#define BATCH   2
#define SEQ     2048
#define BSROWS  (BATCH*SEQ)   // 4096
#define EPSV    1e-5f

// ---------------- scratch (no cudaMalloc allowed) ----------------
static __device__ float g_h   [(size_t)BSROWS*D_MODEL];
static __device__ float g_q   [(size_t)BSROWS*D_MODEL];
static __device__ float g_k   [(size_t)BSROWS*D_MODEL];
static __device__ float g_v   [(size_t)BSROWS*D_MODEL];
static __device__ float g_attn[(size_t)BSROWS*D_MODEL];
static __device__ float g_y   [(size_t)BSROWS*D_MODEL];
static __device__ float g_u   [(size_t)BSROWS*D_FF];
static __device__ float g_g   [(size_t)BSROWS*D_FF];

// ---------------- common MMA helpers ----------------
__device__ __forceinline__ unsigned f2tf32(float f) {
    unsigned u;
    asm("cvt.rna.tf32.f32 %0, %1;\n" : "=r"(u) : "f"(f));
    return u;
}

__device__ __forceinline__ void mma_tf32(float* d, const unsigned* a, const unsigned* b) {
    asm volatile(
        "mma.sync.aligned.m16n8k8.row.col.f32.tf32.tf32.f32 "
        "{%0,%1,%2,%3}, {%4,%5,%6,%7}, {%8,%9}, {%0,%1,%2,%3};\n"
        : "+f"(d[0]), "+f"(d[1]), "+f"(d[2]), "+f"(d[3])
        : "r"(a[0]), "r"(a[1]), "r"(a[2]), "r"(a[3]), "r"(b[0]), "r"(b[1]));
}

__device__ __forceinline__ void cp_a16(unsigned d, const float* s) {
    asm volatile("cp.async.cg.shared.global [%0], [%1], 16;\n" :: "r"(d), "l"(s));
}

// ---------------- RMSNorm: one block per row ----------------
__global__ void rmsnorm_k(const float* __restrict__ x, const float* __restrict__ gains,
                          float* __restrict__ o) {
    int row = blockIdx.x;
    const float* xr = x + (size_t)row * D_MODEL;
    float*       orow = o + (size_t)row * D_MODEL;
    float s = 0.f;
    for (int i = threadIdx.x; i < D_MODEL; i += 256) { float v = xr[i]; s += v * v; }
    #pragma unroll
    for (int off = 16; off; off >>= 1) s += __shfl_xor_sync(0xffffffffu, s, off);
    __shared__ float ws[8];
    __shared__ float rinv;
    if ((threadIdx.x & 31) == 0) ws[threadIdx.x >> 5] = s;
    __syncthreads();
    if (threadIdx.x == 0) {
        float t = 0.f;
        #pragma unroll
        for (int i = 0; i < 8; i++) t += ws[i];
        rinv = rsqrtf(t / (float)D_MODEL + EPSV);
    }
    __syncthreads();
    float r = rinv;
    for (int i = threadIdx.x; i < D_MODEL; i += 256)
        orow[i] = xr[i] * gains[i] * r;
}

// ---------------- TF32 GEMM core: cp.async 2-stage, K-chunk 32 ----------------
// C[128,128 tile] = A[M,K] * B[N,K]^T (+res / rope). fp32 bits fed directly to
// mma.tf32 (HW RZ truncation). Smem row stride 40 words: uint2 fragment loads
// hit banks (8*gid + 2*tig) mod 32 -> all 32 banks once per 16-lane phase,
// conflict-free LDS.64 (stride 36 conflicted: the R14 regression).
// k-slot permutation (slots tig,tig+4 <- physical cols 2tig,2tig+1) applied
// identically to A and B: sum over k unchanged.
#define GSTR 40
#define KSTG (128 * GSTR)               // words per matrix per stage
#define GEMM_SMEM (2 * 2 * KSTG * 4)    // 81920 bytes

__device__ __forceinline__ void gemm_core(const float* __restrict__ A,
                                          const float* __restrict__ B,
                                          const float* __restrict__ res,
                                          float* __restrict__ C,
                                          int N, int K, int bm, int bn, int rope) {
    extern __shared__ unsigned smg[];
    const int t = threadIdx.x;
    const int warp = t >> 5, lane = t & 31;
    const int gid = lane >> 2, tig = lane & 3;
    const int wm = (warp >> 2) * 64, wn = (warp & 3) * 32;

    const int arow = t >> 3;         // 0..31
    const int ac4  = (t & 7) * 4;    // 0..28
    const float* Ag = A + (size_t)(bm + arow) * K + ac4;
    const float* Bg = B + (size_t)(bn + arow) * K + ac4;
    unsigned sbase = (unsigned)__cvta_generic_to_shared(smg);

    auto issue = [&](int s, int kof) {
        unsigned abase = sbase + (unsigned)(s * 2 * KSTG) * 4u;
        unsigned bbase = abase + (unsigned)KSTG * 4u;
        #pragma unroll
        for (int i = 0; i < 4; i++) {
            unsigned off = (unsigned)((arow + i * 32) * GSTR + ac4) * 4u;
            cp_a16(abase + off, Ag + (size_t)(i * 32) * K + kof);
            cp_a16(bbase + off, Bg + (size_t)(i * 32) * K + kof);
        }
        asm volatile("cp.async.commit_group;\n" ::: "memory");
    };

    float acc[4][4][4];
    #pragma unroll
    for (int i = 0; i < 4; i++)
        #pragma unroll
        for (int j = 0; j < 4; j++)
            #pragma unroll
            for (int r = 0; r < 4; r++) acc[i][j][r] = 0.f;

    const int T = K >> 5;
    issue(0, 0);
    for (int kt = 0; kt < T; kt++) {
        asm volatile("cp.async.wait_group 0;\n" ::: "memory");
        __syncthreads();   // stage kt visible; all warps done with prior use of other slot
        if (kt + 1 < T) issue((kt + 1) & 1, (kt + 1) * 32);
        const unsigned* As = smg + (kt & 1) * 2 * KSTG;
        const unsigned* Bs = As + KSTG;
        #pragma unroll
        for (int ks = 0; ks < 4; ks++) {
            const int ko = ks * 8 + tig * 2;   // permuted slot base
            unsigned af[4][4];
            #pragma unroll
            for (int mt = 0; mt < 4; mt++) {
                int r = wm + mt * 16 + gid;
                uint2 lo = *(const uint2*)&As[r * GSTR + ko];
                uint2 hi = *(const uint2*)&As[(r + 8) * GSTR + ko];
                af[mt][0] = lo.x; af[mt][2] = lo.y;
                af[mt][1] = hi.x; af[mt][3] = hi.y;
            }
            unsigned bf[4][2];
            #pragma unroll
            for (int nt = 0; nt < 4; nt++) {
                int c = wn + nt * 8 + gid;
                uint2 bb = *(const uint2*)&Bs[c * GSTR + ko];
                bf[nt][0] = bb.x; bf[nt][1] = bb.y;
            }
            #pragma unroll
            for (int mt = 0; mt < 4; mt++)
                #pragma unroll
                for (int nt = 0; nt < 4; nt++)
                    mma_tf32(acc[mt][nt], af[mt], bf[nt]);
        }
    }

    // epilogue
    #pragma unroll
    for (int mt = 0; mt < 4; mt++) {
        int r0 = bm + wm + mt * 16 + gid;
        #pragma unroll
        for (int nt = 0; nt < 4; nt++) {
            int c0 = bn + wn + nt * 8 + tig * 2;
            float2 v0 = make_float2(acc[mt][nt][0], acc[mt][nt][1]);
            float2 v1 = make_float2(acc[mt][nt][2], acc[mt][nt][3]);
            if (rope) {
                int d = c0 & 63;   // even; pair (d, d+1), j = d/2
                float inv = expf(-(float)d * (9.210340371976184f / 64.f));
                float sn0, cs0, sn1, cs1;
                sincosf((float)(r0 & (SEQ - 1)) * inv, &sn0, &cs0);
                sincosf((float)((r0 + 8) & (SEQ - 1)) * inv, &sn1, &cs1);
                float t0 = v0.x * cs0 - v0.y * sn0;
                v0.y = v0.y * cs0 + v0.x * sn0; v0.x = t0;
                float t1 = v1.x * cs1 - v1.y * sn1;
                v1.y = v1.y * cs1 + v1.x * sn1; v1.x = t1;
            } else if (res) {
                float2 r0v = *(const float2*)&res[(size_t)r0 * N + c0];
                float2 r1v = *(const float2*)&res[(size_t)(r0 + 8) * N + c0];
                v0.x += r0v.x; v0.y += r0v.y;
                v1.x += r1v.x; v1.y += r1v.y;
            }
            *(float2*)&C[(size_t)r0 * N + c0]       = v0;
            *(float2*)&C[(size_t)(r0 + 8) * N + c0] = v1;
        }
    }
}

__global__ __launch_bounds__(256, 2) void gemm_plain(const float* __restrict__ A,
                                                     const float* __restrict__ B,
                                                     const float* __restrict__ res,
                                                     float* __restrict__ C,
                                                     int N, int K) {
    gemm_core(A, B, res, C, N, K, blockIdx.y * 128, blockIdx.x * 128, 0);
}

// fused QKV: grid.x = 24 (8 per matrix); RoPE fused for Q,K
__global__ __launch_bounds__(256, 2) void gemm_qkv(const float* __restrict__ A,
                                                   const float* __restrict__ WQ,
                                                   const float* __restrict__ WK,
                                                   const float* __restrict__ WV,
                                                   float* __restrict__ q,
                                                   float* __restrict__ k,
                                                   float* __restrict__ v) {
    int sel = blockIdx.x >> 3;
    const float* B = (sel == 0) ? WQ : (sel == 1) ? WK : WV;
    float* C       = (sel == 0) ? q  : (sel == 1) ? k  : v;
    gemm_core(A, B, nullptr, C, D_MODEL, D_MODEL,
              blockIdx.y * 128, (blockIdx.x & 7) * 128, sel < 2);
}

// fused FFN up/gate: grid.x = 44 (22 per matrix)
__global__ __launch_bounds__(256, 2) void gemm_ug(const float* __restrict__ A,
                                                  const float* __restrict__ W1,
                                                  const float* __restrict__ W3,
                                                  float* __restrict__ u,
                                                  float* __restrict__ g) {
    int sel = (blockIdx.x >= 22);
    gemm_core(A, sel ? W3 : W1, nullptr, sel ? g : u, D_FF, D_MODEL,
              blockIdx.y * 128, (blockIdx.x - sel * 22) * 128, 0);
}

// ---------------- Flash attention, TF32 tensor cores (unchanged from R11) ----------------
#define ASTR 68
#define ATTN_SMEM ((128 * ASTR + 2 * 64 * ASTR) * 4)
__global__ __launch_bounds__(256) void attn_mma(const float* __restrict__ q,
                                                const float* __restrict__ k,
                                                const float* __restrict__ v,
                                                float* __restrict__ o) {
    extern __shared__ unsigned sm_u[];
    unsigned* Qs = sm_u;
    unsigned* Ps = sm_u;
    unsigned* Ks = sm_u + 128 * ASTR;
    unsigned* Vs = Ks + 64 * ASTR;

    const int bh = blockIdx.y;
    const int b  = bh / NHEADS, h = bh % NHEADS;
    const int q0 = blockIdx.x * 128;
    const int t  = threadIdx.x;
    const int warp = t >> 5, lane = t & 31;
    const int gid = lane >> 2, tig = lane & 3;
    const int wr  = warp * 16;

    for (int i = t; i < 128 * 16; i += 256) {
        int r = i >> 4, d4 = i & 15;
        float4 qv = *(const float4*)&q[((size_t)(b * SEQ + q0 + r)) * D_MODEL + h * 64 + d4 * 4];
        *(uint4*)&Qs[r * ASTR + d4 * 4] =
            make_uint4(f2tf32(qv.x * 0.125f), f2tf32(qv.y * 0.125f),
                       f2tf32(qv.z * 0.125f), f2tf32(qv.w * 0.125f));
    }
    __syncthreads();

    unsigned qa[8][4];
    #pragma unroll
    for (int ks = 0; ks < 8; ks++) {
        qa[ks][0] = Qs[(wr + gid) * ASTR + ks * 8 + tig];
        qa[ks][1] = Qs[(wr + gid + 8) * ASTR + ks * 8 + tig];
        qa[ks][2] = Qs[(wr + gid) * ASTR + ks * 8 + tig + 4];
        qa[ks][3] = Qs[(wr + gid + 8) * ASTR + ks * 8 + tig + 4];
    }

    float oacc[8][4];
    #pragma unroll
    for (int nt = 0; nt < 8; nt++)
        #pragma unroll
        for (int e = 0; e < 4; e++) oacc[nt][e] = 0.f;
    float m0 = -1e30f, m1 = -1e30f, l0 = 0.f, l1 = 0.f;

    const int r0 = q0 + wr + gid;
    const int r1 = r0 + 8;
    const int ntiles = q0 / 64 + 2;

    for (int kt = 0; kt < ntiles; kt++) {
        const int k0 = kt * 64;
        __syncthreads();
        for (int i = t; i < 64 * 16; i += 256) {
            int r = i >> 4, d4 = i & 15;
            size_t gi = ((size_t)(b * SEQ + k0 + r)) * D_MODEL + h * 64 + d4 * 4;
            float4 kv = *(const float4*)&k[gi];
            *(uint4*)&Ks[r * ASTR + d4 * 4] =
                make_uint4(f2tf32(kv.x), f2tf32(kv.y), f2tf32(kv.z), f2tf32(kv.w));
            float4 vv = *(const float4*)&v[gi];
            Vs[(d4 * 4 + 0) * ASTR + r] = f2tf32(vv.x);
            Vs[(d4 * 4 + 1) * ASTR + r] = f2tf32(vv.y);
            Vs[(d4 * 4 + 2) * ASTR + r] = f2tf32(vv.z);
            Vs[(d4 * 4 + 3) * ASTR + r] = f2tf32(vv.w);
        }
        __syncthreads();

        float sacc[8][4];
        #pragma unroll
        for (int nt = 0; nt < 8; nt++) {
            sacc[nt][0] = sacc[nt][1] = sacc[nt][2] = sacc[nt][3] = 0.f;
            #pragma unroll
            for (int ks = 0; ks < 8; ks++) {
                unsigned kb[2];
                kb[0] = Ks[(nt * 8 + gid) * ASTR + ks * 8 + tig];
                kb[1] = Ks[(nt * 8 + gid) * ASTR + ks * 8 + tig + 4];
                mma_tf32(sacc[nt], qa[ks], kb);
            }
        }

        if (k0 + 63 > q0) {
            #pragma unroll
            for (int nt = 0; nt < 8; nt++) {
                int c0 = k0 + nt * 8 + tig * 2;
                if (c0     > r0) sacc[nt][0] = -1e30f;
                if (c0 + 1 > r0) sacc[nt][1] = -1e30f;
                if (c0     > r1) sacc[nt][2] = -1e30f;
                if (c0 + 1 > r1) sacc[nt][3] = -1e30f;
            }
        }

        float m0loc = -1e30f, m1loc = -1e30f;
        #pragma unroll
        for (int nt = 0; nt < 8; nt++) {
            m0loc = fmaxf(m0loc, fmaxf(sacc[nt][0], sacc[nt][1]));
            m1loc = fmaxf(m1loc, fmaxf(sacc[nt][2], sacc[nt][3]));
        }
        m0loc = fmaxf(m0loc, __shfl_xor_sync(0xffffffffu, m0loc, 1));
        m0loc = fmaxf(m0loc, __shfl_xor_sync(0xffffffffu, m0loc, 2));
        m1loc = fmaxf(m1loc, __shfl_xor_sync(0xffffffffu, m1loc, 1));
        m1loc = fmaxf(m1loc, __shfl_xor_sync(0xffffffffu, m1loc, 2));
        float mn0 = fmaxf(m0, m0loc), mn1 = fmaxf(m1, m1loc);
        float corr0 = __expf(m0 - mn0), corr1 = __expf(m1 - mn1);
        float ps0 = 0.f, ps1 = 0.f;
        #pragma unroll
        for (int nt = 0; nt < 8; nt++) {
            float p0 = __expf(sacc[nt][0] - mn0);
            float p1 = __expf(sacc[nt][1] - mn0);
            float p2 = __expf(sacc[nt][2] - mn1);
            float p3 = __expf(sacc[nt][3] - mn1);
            ps0 += p0 + p1; ps1 += p2 + p3;
            *(uint2*)&Ps[(wr + gid) * ASTR + nt * 8 + tig * 2] =
                make_uint2(f2tf32(p0), f2tf32(p1));
            *(uint2*)&Ps[(wr + gid + 8) * ASTR + nt * 8 + tig * 2] =
                make_uint2(f2tf32(p2), f2tf32(p3));
        }
        ps0 += __shfl_xor_sync(0xffffffffu, ps0, 1);
        ps0 += __shfl_xor_sync(0xffffffffu, ps0, 2);
        ps1 += __shfl_xor_sync(0xffffffffu, ps1, 1);
        ps1 += __shfl_xor_sync(0xffffffffu, ps1, 2);
        l0 = l0 * corr0 + ps0;
        l1 = l1 * corr1 + ps1;
        m0 = mn0; m1 = mn1;
        #pragma unroll
        for (int nt = 0; nt < 8; nt++) {
            oacc[nt][0] *= corr0; oacc[nt][1] *= corr0;
            oacc[nt][2] *= corr1; oacc[nt][3] *= corr1;
        }
        __syncwarp();

        #pragma unroll
        for (int ks = 0; ks < 8; ks++) {
            unsigned pa[4];
            pa[0] = Ps[(wr + gid) * ASTR + ks * 8 + tig];
            pa[1] = Ps[(wr + gid + 8) * ASTR + ks * 8 + tig];
            pa[2] = Ps[(wr + gid) * ASTR + ks * 8 + tig + 4];
            pa[3] = Ps[(wr + gid + 8) * ASTR + ks * 8 + tig + 4];
            #pragma unroll
            for (int nt = 0; nt < 8; nt++) {
                unsigned vb[2];
                vb[0] = Vs[(nt * 8 + gid) * ASTR + ks * 8 + tig];
                vb[1] = Vs[(nt * 8 + gid) * ASTR + ks * 8 + tig + 4];
                mma_tf32(oacc[nt], pa, vb);
            }
        }
    }

    float i0 = 1.f / l0, i1 = 1.f / l1;
    size_t ob0 = ((size_t)(b * SEQ + r0)) * D_MODEL + h * 64;
    size_t ob1 = ((size_t)(b * SEQ + r1)) * D_MODEL + h * 64;
    #pragma unroll
    for (int nt = 0; nt < 8; nt++) {
        int c0 = nt * 8 + tig * 2;
        *(float2*)&o[ob0 + c0] = make_float2(oacc[nt][0] * i0, oacc[nt][1] * i0);
        *(float2*)&o[ob1 + c0] = make_float2(oacc[nt][2] * i1, oacc[nt][3] * i1);
    }
}

// ---------------- SwiGLU elementwise: u <- u*sigmoid(u)*g (float4) ----------------
__global__ void swiglu_k(float4* __restrict__ u, const float4* __restrict__ g) {
    size_t i = (size_t)blockIdx.x * blockDim.x + threadIdx.x;
    if (i < (size_t)BSROWS * D_FF / 4) {
        float4 uv = u[i];
        float4 gv = g[i];
        uv.x = uv.x / (1.f + __expf(-uv.x)) * gv.x;
        uv.y = uv.y / (1.f + __expf(-uv.y)) * gv.y;
        uv.z = uv.z / (1.f + __expf(-uv.z)) * gv.z;
        uv.w = uv.w / (1.f + __expf(-uv.w)) * gv.w;
        u[i] = uv;
    }
}

// ---------------- launch ----------------
extern "C" void kernel_launch(void* const* d_in, const int* in_sizes, int n_in,
                              void* d_out, int out_size) {
    const float* x      = (const float*)d_in[0];
    const float* gains1 = (const float*)d_in[1];
    const float* gains2 = (const float*)d_in[2];
    const float* WQ     = (const float*)d_in[3];
    const float* WK     = (const float*)d_in[4];
    const float* WV     = (const float*)d_in[5];
    const float* WO     = (const float*)d_in[6];
    const float* W1     = (const float*)d_in[7];
    const float* W2     = (const float*)d_in[8];
    const float* W3     = (const float*)d_in[9];
    float* out = (float*)d_out;

    float *h, *q, *k, *v, *attn, *y, *u, *g;
    cudaGetSymbolAddress((void**)&h,    g_h);
    cudaGetSymbolAddress((void**)&q,    g_q);
    cudaGetSymbolAddress((void**)&k,    g_k);
    cudaGetSymbolAddress((void**)&v,    g_v);
    cudaGetSymbolAddress((void**)&attn, g_attn);
    cudaGetSymbolAddress((void**)&y,    g_y);
    cudaGetSymbolAddress((void**)&u,    g_u);
    cudaGetSymbolAddress((void**)&g,    g_g);

    cudaFuncSetAttribute(gemm_plain, cudaFuncAttributeMaxDynamicSharedMemorySize, GEMM_SMEM);
    cudaFuncSetAttribute(gemm_qkv,   cudaFuncAttributeMaxDynamicSharedMemorySize, GEMM_SMEM);
    cudaFuncSetAttribute(gemm_ug,    cudaFuncAttributeMaxDynamicSharedMemorySize, GEMM_SMEM);
    cudaFuncSetAttribute(attn_mma,   cudaFuncAttributeMaxDynamicSharedMemorySize, ATTN_SMEM);

    // 1. pre-attention RMSNorm
    rmsnorm_k<<<BSROWS, 256>>>(x, gains1, h);

    // 2. QKV projections + fused RoPE (one launch)
    gemm_qkv<<<dim3(24, BSROWS / 128), 256, GEMM_SMEM>>>(h, WQ, WK, WV, q, k, v);

    // 3. causal flash attention (TF32 tensor cores)
    attn_mma<<<dim3(SEQ / 128, BATCH * NHEADS), 256, ATTN_SMEM>>>(q, k, v, attn);

    // 4. output projection + residual
    gemm_plain<<<dim3(D_MODEL / 128, BSROWS / 128), 256, GEMM_SMEM>>>(
        attn, WO, x, y, D_MODEL, D_MODEL);

    // 5. pre-FFN RMSNorm
    rmsnorm_k<<<BSROWS, 256>>>(y, gains2, h);

    // 6. FFN up + gate (one launch)
    gemm_ug<<<dim3(44, BSROWS / 128), 256, GEMM_SMEM>>>(h, W1, W3, u, g);

    // 7. SwiGLU
    size_t nsw = (size_t)BSROWS * D_FF / 4;
    swiglu_k<<<(int)((nsw + 255) / 256), 256>>>((float4*)u, (const float4*)g);

    // 8. down projection + residual -> out
    gemm_plain<<<dim3(D_MODEL / 128, BSROWS / 128), 256, GEMM_SMEM>>>(
        u, W2, y, out, D_MODEL, D_FF);
}

// round 17
// speedup vs baseline: 1.2107x; 1.0140x over previous
#include <cuda_runtime.h>
#include <math.h>

#define D_MODEL 1024
#define D_FF    2816
#define NHEADS  16
#define DK      64
#define BATCH   2
#define SEQ     2048
#define BSROWS  (BATCH*SEQ)   // 4096
#define EPSV    1e-5f

// ---------------- scratch (no cudaMalloc allowed) ----------------
static __device__ float g_h   [(size_t)BSROWS*D_MODEL];
static __device__ float g_q   [(size_t)BSROWS*D_MODEL];
static __device__ float g_k   [(size_t)BSROWS*D_MODEL];
static __device__ float g_v   [(size_t)BSROWS*D_MODEL];
static __device__ float g_attn[(size_t)BSROWS*D_MODEL];
static __device__ float g_y   [(size_t)BSROWS*D_MODEL];
static __device__ float g_u   [(size_t)BSROWS*D_FF];
static __device__ float g_g   [(size_t)BSROWS*D_FF];

// ---------------- common MMA helpers ----------------
__device__ __forceinline__ unsigned f2tf32(float f) {
    unsigned u;
    asm("cvt.rna.tf32.f32 %0, %1;\n" : "=r"(u) : "f"(f));
    return u;
}

__device__ __forceinline__ void mma_tf32(float* d, const unsigned* a, const unsigned* b) {
    asm volatile(
        "mma.sync.aligned.m16n8k8.row.col.f32.tf32.tf32.f32 "
        "{%0,%1,%2,%3}, {%4,%5,%6,%7}, {%8,%9}, {%0,%1,%2,%3};\n"
        : "+f"(d[0]), "+f"(d[1]), "+f"(d[2]), "+f"(d[3])
        : "r"(a[0]), "r"(a[1]), "r"(a[2]), "r"(a[3]), "r"(b[0]), "r"(b[1]));
}

__device__ __forceinline__ void cp_a16(unsigned d, const float* s) {
    asm volatile("cp.async.cg.shared.global [%0], [%1], 16;\n" :: "r"(d), "l"(s));
}

// ---------------- RMSNorm: one block per row ----------------
__global__ void rmsnorm_k(const float* __restrict__ x, const float* __restrict__ gains,
                          float* __restrict__ o) {
    int row = blockIdx.x;
    const float* xr = x + (size_t)row * D_MODEL;
    float*       orow = o + (size_t)row * D_MODEL;
    float s = 0.f;
    for (int i = threadIdx.x; i < D_MODEL; i += 256) { float v = xr[i]; s += v * v; }
    #pragma unroll
    for (int off = 16; off; off >>= 1) s += __shfl_xor_sync(0xffffffffu, s, off);
    __shared__ float ws[8];
    __shared__ float rinv;
    if ((threadIdx.x & 31) == 0) ws[threadIdx.x >> 5] = s;
    __syncthreads();
    if (threadIdx.x == 0) {
        float t = 0.f;
        #pragma unroll
        for (int i = 0; i < 8; i++) t += ws[i];
        rinv = rsqrtf(t / (float)D_MODEL + EPSV);
    }
    __syncthreads();
    float r = rinv;
    for (int i = threadIdx.x; i < D_MODEL; i += 256)
        orow[i] = xr[i] * gains[i] * r;
}

// ---------------- TF32 GEMM core: cp.async 2-stage, K-chunk 32 ----------------
// C[128,128 tile] = A[M,K] * B[N,K]^T (+res / rope). fp32 bits fed directly to
// mma.tf32 (HW RZ truncation). Smem row stride 40 words: uint2 fragment loads
// hit banks (8*gid + 2*tig) mod 32 -> all 32 banks once per 16-lane phase,
// conflict-free LDS.64 (stride 36 conflicted: the R14 regression).
// k-slot permutation (slots tig,tig+4 <- physical cols 2tig,2tig+1) applied
// identically to A and B: sum over k unchanged.
#define GSTR 40
#define KSTG (128 * GSTR)               // words per matrix per stage
#define GEMM_SMEM (2 * 2 * KSTG * 4)    // 81920 bytes

__device__ __forceinline__ void gemm_core(const float* __restrict__ A,
                                          const float* __restrict__ B,
                                          const float* __restrict__ res,
                                          float* __restrict__ C,
                                          int N, int K, int bm, int bn, int rope) {
    extern __shared__ unsigned smg[];
    const int t = threadIdx.x;
    const int warp = t >> 5, lane = t & 31;
    const int gid = lane >> 2, tig = lane & 3;
    const int wm = (warp >> 2) * 64, wn = (warp & 3) * 32;

    const int arow = t >> 3;         // 0..31
    const int ac4  = (t & 7) * 4;    // 0..28
    const float* Ag = A + (size_t)(bm + arow) * K + ac4;
    const float* Bg = B + (size_t)(bn + arow) * K + ac4;
    unsigned sbase = (unsigned)__cvta_generic_to_shared(smg);

    auto issue = [&](int s, int kof) {
        unsigned abase = sbase + (unsigned)(s * 2 * KSTG) * 4u;
        unsigned bbase = abase + (unsigned)KSTG * 4u;
        #pragma unroll
        for (int i = 0; i < 4; i++) {
            unsigned off = (unsigned)((arow + i * 32) * GSTR + ac4) * 4u;
            cp_a16(abase + off, Ag + (size_t)(i * 32) * K + kof);
            cp_a16(bbase + off, Bg + (size_t)(i * 32) * K + kof);
        }
        asm volatile("cp.async.commit_group;\n" ::: "memory");
    };

    float acc[4][4][4];
    #pragma unroll
    for (int i = 0; i < 4; i++)
        #pragma unroll
        for (int j = 0; j < 4; j++)
            #pragma unroll
            for (int r = 0; r < 4; r++) acc[i][j][r] = 0.f;

    const int T = K >> 5;
    issue(0, 0);
    for (int kt = 0; kt < T; kt++) {
        asm volatile("cp.async.wait_group 0;\n" ::: "memory");
        __syncthreads();   // stage kt visible; all warps done with prior use of other slot
        if (kt + 1 < T) issue((kt + 1) & 1, (kt + 1) * 32);
        const unsigned* As = smg + (kt & 1) * 2 * KSTG;
        const unsigned* Bs = As + KSTG;
        #pragma unroll
        for (int ks = 0; ks < 4; ks++) {
            const int ko = ks * 8 + tig * 2;   // permuted slot base
            unsigned af[4][4];
            #pragma unroll
            for (int mt = 0; mt < 4; mt++) {
                int r = wm + mt * 16 + gid;
                uint2 lo = *(const uint2*)&As[r * GSTR + ko];
                uint2 hi = *(const uint2*)&As[(r + 8) * GSTR + ko];
                af[mt][0] = lo.x; af[mt][2] = lo.y;
                af[mt][1] = hi.x; af[mt][3] = hi.y;
            }
            unsigned bf[4][2];
            #pragma unroll
            for (int nt = 0; nt < 4; nt++) {
                int c = wn + nt * 8 + gid;
                uint2 bb = *(const uint2*)&Bs[c * GSTR + ko];
                bf[nt][0] = bb.x; bf[nt][1] = bb.y;
            }
            #pragma unroll
            for (int mt = 0; mt < 4; mt++)
                #pragma unroll
                for (int nt = 0; nt < 4; nt++)
                    mma_tf32(acc[mt][nt], af[mt], bf[nt]);
        }
    }

    // epilogue
    #pragma unroll
    for (int mt = 0; mt < 4; mt++) {
        int r0 = bm + wm + mt * 16 + gid;
        #pragma unroll
        for (int nt = 0; nt < 4; nt++) {
            int c0 = bn + wn + nt * 8 + tig * 2;
            float2 v0 = make_float2(acc[mt][nt][0], acc[mt][nt][1]);
            float2 v1 = make_float2(acc[mt][nt][2], acc[mt][nt][3]);
            if (rope) {
                int d = c0 & 63;   // even; pair (d, d+1), j = d/2
                float inv = expf(-(float)d * (9.210340371976184f / 64.f));
                float sn0, cs0, sn1, cs1;
                sincosf((float)(r0 & (SEQ - 1)) * inv, &sn0, &cs0);
                sincosf((float)((r0 + 8) & (SEQ - 1)) * inv, &sn1, &cs1);
                float t0 = v0.x * cs0 - v0.y * sn0;
                v0.y = v0.y * cs0 + v0.x * sn0; v0.x = t0;
                float t1 = v1.x * cs1 - v1.y * sn1;
                v1.y = v1.y * cs1 + v1.x * sn1; v1.x = t1;
            } else if (res) {
                float2 r0v = *(const float2*)&res[(size_t)r0 * N + c0];
                float2 r1v = *(const float2*)&res[(size_t)(r0 + 8) * N + c0];
                v0.x += r0v.x; v0.y += r0v.y;
                v1.x += r1v.x; v1.y += r1v.y;
            }
            *(float2*)&C[(size_t)r0 * N + c0]       = v0;
            *(float2*)&C[(size_t)(r0 + 8) * N + c0] = v1;
        }
    }
}

__global__ __launch_bounds__(256, 2) void gemm_plain(const float* __restrict__ A,
                                                     const float* __restrict__ B,
                                                     const float* __restrict__ res,
                                                     float* __restrict__ C,
                                                     int N, int K) {
    gemm_core(A, B, res, C, N, K, blockIdx.y * 128, blockIdx.x * 128, 0);
}

// fused QKV: grid.x = 24 (8 per matrix); RoPE fused for Q,K
__global__ __launch_bounds__(256, 2) void gemm_qkv(const float* __restrict__ A,
                                                   const float* __restrict__ WQ,
                                                   const float* __restrict__ WK,
                                                   const float* __restrict__ WV,
                                                   float* __restrict__ q,
                                                   float* __restrict__ k,
                                                   float* __restrict__ v) {
    int sel = blockIdx.x >> 3;
    const float* B = (sel == 0) ? WQ : (sel == 1) ? WK : WV;
    float* C       = (sel == 0) ? q  : (sel == 1) ? k  : v;
    gemm_core(A, B, nullptr, C, D_MODEL, D_MODEL,
              blockIdx.y * 128, (blockIdx.x & 7) * 128, sel < 2);
}

// fused FFN up/gate: grid.x = 44 (22 per matrix)
__global__ __launch_bounds__(256, 2) void gemm_ug(const float* __restrict__ A,
                                                  const float* __restrict__ W1,
                                                  const float* __restrict__ W3,
                                                  float* __restrict__ u,
                                                  float* __restrict__ g) {
    int sel = (blockIdx.x >= 22);
    gemm_core(A, sel ? W3 : W1, nullptr, sel ? g : u, D_FF, D_MODEL,
              blockIdx.y * 128, (blockIdx.x - sel * 22) * 128, 0);
}

// ---------------- Flash attention, TF32 tensor cores (unchanged from R11) ----------------
#define ASTR 68
#define ATTN_SMEM ((128 * ASTR + 2 * 64 * ASTR) * 4)
__global__ __launch_bounds__(256) void attn_mma(const float* __restrict__ q,
                                                const float* __restrict__ k,
                                                const float* __restrict__ v,
                                                float* __restrict__ o) {
    extern __shared__ unsigned sm_u[];
    unsigned* Qs = sm_u;
    unsigned* Ps = sm_u;
    unsigned* Ks = sm_u + 128 * ASTR;
    unsigned* Vs = Ks + 64 * ASTR;

    const int bh = blockIdx.y;
    const int b  = bh / NHEADS, h = bh % NHEADS;
    const int q0 = blockIdx.x * 128;
    const int t  = threadIdx.x;
    const int warp = t >> 5, lane = t & 31;
    const int gid = lane >> 2, tig = lane & 3;
    const int wr  = warp * 16;

    for (int i = t; i < 128 * 16; i += 256) {
        int r = i >> 4, d4 = i & 15;
        float4 qv = *(const float4*)&q[((size_t)(b * SEQ + q0 + r)) * D_MODEL + h * 64 + d4 * 4];
        *(uint4*)&Qs[r * ASTR + d4 * 4] =
            make_uint4(f2tf32(qv.x * 0.125f), f2tf32(qv.y * 0.125f),
                       f2tf32(qv.z * 0.125f), f2tf32(qv.w * 0.125f));
    }
    __syncthreads();

    unsigned qa[8][4];
    #pragma unroll
    for (int ks = 0; ks < 8; ks++) {
        qa[ks][0] = Qs[(wr + gid) * ASTR + ks * 8 + tig];
        qa[ks][1] = Qs[(wr + gid + 8) * ASTR + ks * 8 + tig];
        qa[ks][2] = Qs[(wr + gid) * ASTR + ks * 8 + tig + 4];
        qa[ks][3] = Qs[(wr + gid + 8) * ASTR + ks * 8 + tig + 4];
    }

    float oacc[8][4];
    #pragma unroll
    for (int nt = 0; nt < 8; nt++)
        #pragma unroll
        for (int e = 0; e < 4; e++) oacc[nt][e] = 0.f;
    float m0 = -1e30f, m1 = -1e30f, l0 = 0.f, l1 = 0.f;

    const int r0 = q0 + wr + gid;
    const int r1 = r0 + 8;
    const int ntiles = q0 / 64 + 2;

    for (int kt = 0; kt < ntiles; kt++) {
        const int k0 = kt * 64;
        __syncthreads();
        for (int i = t; i < 64 * 16; i += 256) {
            int r = i >> 4, d4 = i & 15;
            size_t gi = ((size_t)(b * SEQ + k0 + r)) * D_MODEL + h * 64 + d4 * 4;
            float4 kv = *(const float4*)&k[gi];
            *(uint4*)&Ks[r * ASTR + d4 * 4] =
                make_uint4(f2tf32(kv.x), f2tf32(kv.y), f2tf32(kv.z), f2tf32(kv.w));
            float4 vv = *(const float4*)&v[gi];
            Vs[(d4 * 4 + 0) * ASTR + r] = f2tf32(vv.x);
            Vs[(d4 * 4 + 1) * ASTR + r] = f2tf32(vv.y);
            Vs[(d4 * 4 + 2) * ASTR + r] = f2tf32(vv.z);
            Vs[(d4 * 4 + 3) * ASTR + r] = f2tf32(vv.w);
        }
        __syncthreads();

        float sacc[8][4];
        #pragma unroll
        for (int nt = 0; nt < 8; nt++) {
            sacc[nt][0] = sacc[nt][1] = sacc[nt][2] = sacc[nt][3] = 0.f;
            #pragma unroll
            for (int ks = 0; ks < 8; ks++) {
                unsigned kb[2];
                kb[0] = Ks[(nt * 8 + gid) * ASTR + ks * 8 + tig];
                kb[1] = Ks[(nt * 8 + gid) * ASTR + ks * 8 + tig + 4];
                mma_tf32(sacc[nt], qa[ks], kb);
            }
        }

        if (k0 + 63 > q0) {
            #pragma unroll
            for (int nt = 0; nt < 8; nt++) {
                int c0 = k0 + nt * 8 + tig * 2;
                if (c0     > r0) sacc[nt][0] = -1e30f;
                if (c0 + 1 > r0) sacc[nt][1] = -1e30f;
                if (c0     > r1) sacc[nt][2] = -1e30f;
                if (c0 + 1 > r1) sacc[nt][3] = -1e30f;
            }
        }

        float m0loc = -1e30f, m1loc = -1e30f;
        #pragma unroll
        for (int nt = 0; nt < 8; nt++) {
            m0loc = fmaxf(m0loc, fmaxf(sacc[nt][0], sacc[nt][1]));
            m1loc = fmaxf(m1loc, fmaxf(sacc[nt][2], sacc[nt][3]));
        }
        m0loc = fmaxf(m0loc, __shfl_xor_sync(0xffffffffu, m0loc, 1));
        m0loc = fmaxf(m0loc, __shfl_xor_sync(0xffffffffu, m0loc, 2));
        m1loc = fmaxf(m1loc, __shfl_xor_sync(0xffffffffu, m1loc, 1));
        m1loc = fmaxf(m1loc, __shfl_xor_sync(0xffffffffu, m1loc, 2));
        float mn0 = fmaxf(m0, m0loc), mn1 = fmaxf(m1, m1loc);
        float corr0 = __expf(m0 - mn0), corr1 = __expf(m1 - mn1);
        float ps0 = 0.f, ps1 = 0.f;
        #pragma unroll
        for (int nt = 0; nt < 8; nt++) {
            float p0 = __expf(sacc[nt][0] - mn0);
            float p1 = __expf(sacc[nt][1] - mn0);
            float p2 = __expf(sacc[nt][2] - mn1);
            float p3 = __expf(sacc[nt][3] - mn1);
            ps0 += p0 + p1; ps1 += p2 + p3;
            *(uint2*)&Ps[(wr + gid) * ASTR + nt * 8 + tig * 2] =
                make_uint2(f2tf32(p0), f2tf32(p1));
            *(uint2*)&Ps[(wr + gid + 8) * ASTR + nt * 8 + tig * 2] =
                make_uint2(f2tf32(p2), f2tf32(p3));
        }
        ps0 += __shfl_xor_sync(0xffffffffu, ps0, 1);
        ps0 += __shfl_xor_sync(0xffffffffu, ps0, 2);
        ps1 += __shfl_xor_sync(0xffffffffu, ps1, 1);
        ps1 += __shfl_xor_sync(0xffffffffu, ps1, 2);
        l0 = l0 * corr0 + ps0;
        l1 = l1 * corr1 + ps1;
        m0 = mn0; m1 = mn1;
        #pragma unroll
        for (int nt = 0; nt < 8; nt++) {
            oacc[nt][0] *= corr0; oacc[nt][1] *= corr0;
            oacc[nt][2] *= corr1; oacc[nt][3] *= corr1;
        }
        __syncwarp();

        #pragma unroll
        for (int ks = 0; ks < 8; ks++) {
            unsigned pa[4];
            pa[0] = Ps[(wr + gid) * ASTR + ks * 8 + tig];
            pa[1] = Ps[(wr + gid + 8) * ASTR + ks * 8 + tig];
            pa[2] = Ps[(wr + gid) * ASTR + ks * 8 + tig + 4];
            pa[3] = Ps[(wr + gid + 8) * ASTR + ks * 8 + tig + 4];
            #pragma unroll
            for (int nt = 0; nt < 8; nt++) {
                unsigned vb[2];
                vb[0] = Vs[(nt * 8 + gid) * ASTR + ks * 8 + tig];
                vb[1] = Vs[(nt * 8 + gid) * ASTR + ks * 8 + tig + 4];
                mma_tf32(oacc[nt], pa, vb);
            }
        }
    }

    float i0 = 1.f / l0, i1 = 1.f / l1;
    size_t ob0 = ((size_t)(b * SEQ + r0)) * D_MODEL + h * 64;
    size_t ob1 = ((size_t)(b * SEQ + r1)) * D_MODEL + h * 64;
    #pragma unroll
    for (int nt = 0; nt < 8; nt++) {
        int c0 = nt * 8 + tig * 2;
        *(float2*)&o[ob0 + c0] = make_float2(oacc[nt][0] * i0, oacc[nt][1] * i0);
        *(float2*)&o[ob1 + c0] = make_float2(oacc[nt][2] * i1, oacc[nt][3] * i1);
    }
}

// ---------------- SwiGLU elementwise: u <- u*sigmoid(u)*g (float4) ----------------
__global__ void swiglu_k(float4* __restrict__ u, const float4* __restrict__ g) {
    size_t i = (size_t)blockIdx.x * blockDim.x + threadIdx.x;
    if (i < (size_t)BSROWS * D_FF / 4) {
        float4 uv = u[i];
        float4 gv = g[i];
        uv.x = uv.x / (1.f + __expf(-uv.x)) * gv.x;
        uv.y = uv.y / (1.f + __expf(-uv.y)) * gv.y;
        uv.z = uv.z / (1.f + __expf(-uv.z)) * gv.z;
        uv.w = uv.w / (1.f + __expf(-uv.w)) * gv.w;
        u[i] = uv;
    }
}

// ---------------- launch ----------------
extern "C" void kernel_launch(void* const* d_in, const int* in_sizes, int n_in,
                              void* d_out, int out_size) {
    const float* x      = (const float*)d_in[0];
    const float* gains1 = (const float*)d_in[1];
    const float* gains2 = (const float*)d_in[2];
    const float* WQ     = (const float*)d_in[3];
    const float* WK     = (const float*)d_in[4];
    const float* WV     = (const float*)d_in[5];
    const float* WO     = (const float*)d_in[6];
    const float* W1     = (const float*)d_in[7];
    const float* W2     = (const float*)d_in[8];
    const float* W3     = (const float*)d_in[9];
    float* out = (float*)d_out;

    float *h, *q, *k, *v, *attn, *y, *u, *g;
    cudaGetSymbolAddress((void**)&h,    g_h);
    cudaGetSymbolAddress((void**)&q,    g_q);
    cudaGetSymbolAddress((void**)&k,    g_k);
    cudaGetSymbolAddress((void**)&v,    g_v);
    cudaGetSymbolAddress((void**)&attn, g_attn);
    cudaGetSymbolAddress((void**)&y,    g_y);
    cudaGetSymbolAddress((void**)&u,    g_u);
    cudaGetSymbolAddress((void**)&g,    g_g);

    cudaFuncSetAttribute(gemm_plain, cudaFuncAttributeMaxDynamicSharedMemorySize, GEMM_SMEM);
    cudaFuncSetAttribute(gemm_qkv,   cudaFuncAttributeMaxDynamicSharedMemorySize, GEMM_SMEM);
    cudaFuncSetAttribute(gemm_ug,    cudaFuncAttributeMaxDynamicSharedMemorySize, GEMM_SMEM);
    cudaFuncSetAttribute(attn_mma,   cudaFuncAttributeMaxDynamicSharedMemorySize, ATTN_SMEM);

    // 1. pre-attention RMSNorm
    rmsnorm_k<<<BSROWS, 256>>>(x, gains1, h);

    // 2. QKV projections + fused RoPE (one launch)
    gemm_qkv<<<dim3(24, BSROWS / 128), 256, GEMM_SMEM>>>(h, WQ, WK, WV, q, k, v);

    // 3. causal flash attention (TF32 tensor cores)
    attn_mma<<<dim3(SEQ / 128, BATCH * NHEADS), 256, ATTN_SMEM>>>(q, k, v, attn);

    // 4. output projection + residual
    gemm_plain<<<dim3(D_MODEL / 128, BSROWS / 128), 256, GEMM_SMEM>>>(
        attn, WO, x, y, D_MODEL, D_MODEL);

    // 5. pre-FFN RMSNorm
    rmsnorm_k<<<BSROWS, 256>>>(y, gains2, h);

    // 6. FFN up + gate (one launch)
    gemm_ug<<<dim3(44, BSROWS / 128), 256, GEMM_SMEM>>>(h, W1, W3, u, g);

    // 7. SwiGLU
    size_t nsw = (size_t)BSROWS * D_FF / 4;
    swiglu_k<<<(int)((nsw + 255) / 256), 256>>>((float4*)u, (const float4*)g);

    // 8. down projection + residual -> out
    gemm_plain<<<dim3(D_MODEL / 128, BSROWS / 128), 256, GEMM_SMEM>>>(
        u, W2, y, out, D_MODEL, D_FF);
}